// round 15
// baseline (speedup 1.0000x reference)
#include <cuda_runtime.h>
#include <cuda_bf16.h>
#include <math.h>
#include <stdint.h>

// ---------------------------------------------------------------------------
// Problem constants
// ---------------------------------------------------------------------------
#define NSC   384     // scenes
#define SLEN  64      // sentences per scene
#define DIN   768
#define TSEG  40      // audio/vision segments
#define AIN   128
#define VIN   2048
#define HID   256
#define SSD   512     // 2*HID
#define PADW  400
#define KMAX  6

// ---------------------------------------------------------------------------
// Scratch (one big static device buffer; offsets in floats)
// ---------------------------------------------------------------------------
#define OFF_XG      0ull           // 24576 x 2048
#define OFF_OUTS    50331648ull    // 24576 x 512
#define OFF_E       62914560ull    // 24576 x 512
#define OFF_SEMB    75497472ull    // 384 x 512   scene_emb
#define OFF_XGS     75694080ull    // 384 x 2048
#define OFF_SCREMB  76480512ull    // 384 x 512   script_emb
#define OFF_AUD     76677120ull    // 15360 x 512
#define OFF_VIS     84541440ull    // 15360 x 512
#define OFF_AUDV    92405760ull    // 384 x 512
#define OFF_VISV    92602368ull    // 384 x 512
#define OFF_VA      92798976ull    // 384 x 384
#define OFF_AV      92946432ull    // 384 x 1024
#define OFF_MM      93339648ull    // 384 x 384
#define OFF_SCORES  93487104ull    // 384 x 384
#define OFF_CMEAN   93634560ull    // 384 (+pad)
#define OFF_CORE    93635072ull    // 384 (+pad)
#define OFF_NEI     93635584ull    // 384 (+pad)
#define OFF_NLOG    93636096ull    // 384 x 6 (+pad)
#define OFF_XW      93638656ull    // 384 x 512
#define OFF_GOUT    93835264ull    // 384 x 512
#define OFF_LOGITS  94031872ull    // 384 x 5 (+pad)
#define OFF_PACK    94033920ull    // scene Whh packed: 2*256*256 float4
#define OFF_WPS     94558208ull    // script Whh bf16x2: 2*1024*128 uint
#define OFF_GCNT    94820352ull    // gcn_W transposed 512x512
#define SCR_TOTAL   95082496ull

__device__ __align__(256) float g_scratch[SCR_TOTAL];
__device__ int g_idx[NSC * KMAX];
__device__ int g_keep[NSC];

__device__ __forceinline__ float sigm(float x) { return 1.0f / (1.0f + expf(-x)); }

// ---------------------------------------------------------------------------
// Prep kernels (weight repacking)
// ---------------------------------------------------------------------------

__global__ void prep_scene_whh(const float* __restrict__ Whh, float4* __restrict__ P) {
    int id = blockIdx.x * 256 + threadIdx.x;       // 2*256*256 = 131072
    if (id >= 2 * 256 * 256) return;
    int u = id & 255, k = (id >> 8) & 255, dir = id >> 16;
    const float* W = Whh + (size_t)dir * 1024 * 256;
    float4 v;
    v.x = W[(size_t)(0 * 256 + u) * 256 + k];
    v.y = W[(size_t)(1 * 256 + u) * 256 + k];
    v.z = W[(size_t)(2 * 256 + u) * 256 + k];
    v.w = W[(size_t)(3 * 256 + u) * 256 + k];
    P[id] = v;
}

__global__ void prep_script_whh(const float* __restrict__ Whh, unsigned* __restrict__ Wp) {
    int id = blockIdx.x * 256 + threadIdx.x;       // 2*1024*128 = 262144
    if (id >= 2 * 1024 * 128) return;
    int k2 = id & 127, j = (id >> 7) & 1023, dir = id >> 17;
    size_t base = ((size_t)(dir * 1024 + j)) * 256 + 2 * k2;
    __nv_bfloat162 t;
    t.x = __float2bfloat16(Whh[base]);
    t.y = __float2bfloat16(Whh[base + 1]);
    Wp[id] = *reinterpret_cast<unsigned*>(&t);
}

__global__ void prep_transpose512(const float* __restrict__ W, float* __restrict__ Wt) {
    int id = blockIdx.x * 256 + threadIdx.x;
    if (id >= 512 * 512) return;
    int r = id >> 9, c = id & 511;
    Wt[(size_t)c * 512 + r] = W[id];
}

// ---------------------------------------------------------------------------
// fp32 GEMM: C[M,N] = act(A[M,K] @ B[N,K]^T + bias[N])
// Block tile 128x128, BK=16, 256 threads, 8x8 per thread, double-buffered smem.
// Requirements: M % 128 == 0, K % 16 == 0, lda/ldb % 4 == 0. N bounds-checked.
// act: 0 = none, 1 = tanh. bias may be null.
// ---------------------------------------------------------------------------
__global__ __launch_bounds__(256, 2)
void gemm128(const float* __restrict__ A, const float* __restrict__ B,
             const float* __restrict__ bias, float* __restrict__ C,
             int M, int N, int K, int lda, int ldb, int ldc, int act) {
    __shared__ float As[2][16][132];
    __shared__ float Bs[2][16][132];
    int tid = threadIdx.x;
    int m0 = blockIdx.x * 128, n0 = blockIdx.y * 128;
    int tx = tid & 15, ty = tid >> 4;          // 16x16 thread grid, 8x8 microtile
    int ldr = tid >> 2;                         // 0..63
    int ldk = (tid & 3) * 4;                    // 0,4,8,12

    const float* Ab = A + (size_t)(m0 + ldr) * lda + ldk;
    const float* Bb = B + (size_t)(n0 + ldr) * ldb + ldk;
    bool bv0 = (n0 + ldr) < N;
    bool bv1 = (n0 + ldr + 64) < N;

    float acc[8][8];
#pragma unroll
    for (int i = 0; i < 8; i++)
#pragma unroll
        for (int j = 0; j < 8; j++) acc[i][j] = 0.0f;

    // stage k-tile 0 into buffer 0
    {
        float4 a0 = *reinterpret_cast<const float4*>(Ab);
        float4 a1 = *reinterpret_cast<const float4*>(Ab + (size_t)64 * lda);
        float4 b0 = make_float4(0.f, 0.f, 0.f, 0.f);
        float4 b1 = make_float4(0.f, 0.f, 0.f, 0.f);
        if (bv0) b0 = *reinterpret_cast<const float4*>(Bb);
        if (bv1) b1 = *reinterpret_cast<const float4*>(Bb + (size_t)64 * ldb);
        As[0][ldk + 0][ldr] = a0.x; As[0][ldk + 1][ldr] = a0.y;
        As[0][ldk + 2][ldr] = a0.z; As[0][ldk + 3][ldr] = a0.w;
        As[0][ldk + 0][ldr + 64] = a1.x; As[0][ldk + 1][ldr + 64] = a1.y;
        As[0][ldk + 2][ldr + 64] = a1.z; As[0][ldk + 3][ldr + 64] = a1.w;
        Bs[0][ldk + 0][ldr] = b0.x; Bs[0][ldk + 1][ldr] = b0.y;
        Bs[0][ldk + 2][ldr] = b0.z; Bs[0][ldk + 3][ldr] = b0.w;
        Bs[0][ldk + 0][ldr + 64] = b1.x; Bs[0][ldk + 1][ldr + 64] = b1.y;
        Bs[0][ldk + 2][ldr + 64] = b1.z; Bs[0][ldk + 3][ldr + 64] = b1.w;
    }
    __syncthreads();

    int nk = K >> 4;
    int buf = 0;
    for (int kb = 0; kb < nk; kb++) {
        float4 pa0, pa1, pb0, pb1;
        bool more = (kb + 1 < nk);
        if (more) {
            const float* Ap = Ab + (kb + 1) * 16;
            const float* Bp = Bb + (kb + 1) * 16;
            pa0 = *reinterpret_cast<const float4*>(Ap);
            pa1 = *reinterpret_cast<const float4*>(Ap + (size_t)64 * lda);
            pb0 = make_float4(0.f, 0.f, 0.f, 0.f);
            pb1 = make_float4(0.f, 0.f, 0.f, 0.f);
            if (bv0) pb0 = *reinterpret_cast<const float4*>(Bp);
            if (bv1) pb1 = *reinterpret_cast<const float4*>(Bp + (size_t)64 * ldb);
        }

#pragma unroll
        for (int k = 0; k < 16; k++) {
            float4 av0 = *reinterpret_cast<const float4*>(&As[buf][k][ty * 8]);
            float4 av1 = *reinterpret_cast<const float4*>(&As[buf][k][ty * 8 + 4]);
            float4 bv0r = *reinterpret_cast<const float4*>(&Bs[buf][k][tx * 8]);
            float4 bv1r = *reinterpret_cast<const float4*>(&Bs[buf][k][tx * 8 + 4]);
            float ar[8] = {av0.x, av0.y, av0.z, av0.w, av1.x, av1.y, av1.z, av1.w};
            float br[8] = {bv0r.x, bv0r.y, bv0r.z, bv0r.w, bv1r.x, bv1r.y, bv1r.z, bv1r.w};
#pragma unroll
            for (int i = 0; i < 8; i++)
#pragma unroll
                for (int j = 0; j < 8; j++) acc[i][j] += ar[i] * br[j];
        }

        if (more) {
            int nb = buf ^ 1;
            As[nb][ldk + 0][ldr] = pa0.x; As[nb][ldk + 1][ldr] = pa0.y;
            As[nb][ldk + 2][ldr] = pa0.z; As[nb][ldk + 3][ldr] = pa0.w;
            As[nb][ldk + 0][ldr + 64] = pa1.x; As[nb][ldk + 1][ldr + 64] = pa1.y;
            As[nb][ldk + 2][ldr + 64] = pa1.z; As[nb][ldk + 3][ldr + 64] = pa1.w;
            Bs[nb][ldk + 0][ldr] = pb0.x; Bs[nb][ldk + 1][ldr] = pb0.y;
            Bs[nb][ldk + 2][ldr] = pb0.z; Bs[nb][ldk + 3][ldr] = pb0.w;
            Bs[nb][ldk + 0][ldr + 64] = pb1.x; Bs[nb][ldk + 1][ldr + 64] = pb1.y;
            Bs[nb][ldk + 2][ldr + 64] = pb1.z; Bs[nb][ldk + 3][ldr + 64] = pb1.w;
        }
        __syncthreads();
        buf ^= 1;
    }

    // epilogue
#pragma unroll
    for (int i = 0; i < 8; i++) {
        int row = m0 + ty * 8 + i;
#pragma unroll
        for (int j = 0; j < 8; j++) {
            int col = n0 + tx * 8 + j;
            if (col < N) {
                float v = acc[i][j];
                if (bias) v += bias[col];
                if (act == 1) v = tanhf(v);
                C[(size_t)row * ldc + col] = v;
            }
        }
    }
}

// ---------------------------------------------------------------------------
// Scene BiLSTM recurrence. 128 blocks: dir = bx/64, group = bx%64 (6 scenes).
// ---------------------------------------------------------------------------
__global__ __launch_bounds__(256)
void scene_rec(const float* __restrict__ xg, const float4* __restrict__ P,
               float* __restrict__ outs) {
    int dir = blockIdx.x >> 6;
    int grp = blockIdx.x & 63;
    int u = threadIdx.x;
    int nbase = grp * 6;
    __shared__ float hbuf[2][256][6];
#pragma unroll
    for (int sc = 0; sc < 6; sc++) hbuf[0][u][sc] = 0.0f;
    __syncthreads();
    float c[6] = {0, 0, 0, 0, 0, 0};
    const float4* Pd = P + (size_t)dir * 256 * 256;
    int pb = 0;
    for (int t = 0; t < SLEN; t++) {
        int te = dir ? (SLEN - 1 - t) : t;
        float4 acc[6];
#pragma unroll
        for (int sc = 0; sc < 6; sc++) {
            const float* xr = xg + ((size_t)(nbase + sc) * SLEN + te) * 2048 + dir * 1024 + u;
            acc[sc].x = xr[0];
            acc[sc].y = xr[256];
            acc[sc].z = xr[512];
            acc[sc].w = xr[768];
        }
#pragma unroll 4
        for (int k = 0; k < 256; k++) {
            float4 w = Pd[(size_t)k * 256 + u];
#pragma unroll
            for (int sc = 0; sc < 6; sc++) {
                float hv = hbuf[pb][k][sc];
                acc[sc].x += w.x * hv;
                acc[sc].y += w.y * hv;
                acc[sc].z += w.z * hv;
                acc[sc].w += w.w * hv;
            }
        }
#pragma unroll
        for (int sc = 0; sc < 6; sc++) {
            float ig = sigm(acc[sc].x);
            float fg = sigm(acc[sc].y);
            float gg = tanhf(acc[sc].z);
            float og = sigm(acc[sc].w);
            c[sc] = fg * c[sc] + ig * gg;
            float h = og * tanhf(c[sc]);
            hbuf[pb ^ 1][u][sc] = h;
            outs[((size_t)(nbase + sc) * SLEN + te) * SSD + dir * 256 + u] = h;
        }
        __syncthreads();
        pb ^= 1;
    }
}

// ---------------------------------------------------------------------------
// Attention pooling over sentences -> scene_emb. One block per scene.
// ---------------------------------------------------------------------------
__global__ __launch_bounds__(256)
void attn_pool(const float* __restrict__ E, const float* __restrict__ av,
               const float* __restrict__ outs, const int* __restrict__ lens,
               float* __restrict__ semb) {
    int n = blockIdx.x, tid = threadIdx.x;
    __shared__ float pe[4][64];
    __shared__ float sa[64];
    int s = tid & 63, ch = tid >> 6;
    const float* er = E + ((size_t)n * SLEN + s) * SSD + ch * 128;
    float p = 0.f;
#pragma unroll 8
    for (int h = 0; h < 128; h++) p += er[h] * av[ch * 128 + h];
    pe[ch][s] = p;
    __syncthreads();
    if (tid < 64) {
        int len = lens[n]; if (len < 1) len = 1;
        float e = pe[0][tid] + pe[1][tid] + pe[2][tid] + pe[3][tid];
        sa[tid] = (tid < len) ? e : -1e9f;
    }
    __syncthreads();
    if (tid == 0) {
        float m = sa[0];
        for (int q = 1; q < 64; q++) m = fmaxf(m, sa[q]);
        float ssum = 0.f;
        for (int q = 0; q < 64; q++) { float ex = expf(sa[q] - m); sa[q] = ex; ssum += ex; }
        float inv = 1.0f / ssum;
        for (int q = 0; q < 64; q++) sa[q] *= inv;
    }
    __syncthreads();
    for (int h = tid; h < SSD; h += 256) {
        float a = 0.f;
        const float* orow = outs + (size_t)n * SLEN * SSD + h;
#pragma unroll 8
        for (int q = 0; q < 64; q++) a += sa[q] * orow[(size_t)q * SSD];
        semb[(size_t)n * SSD + h] = a;
    }
}

// ---------------------------------------------------------------------------
// Script BiLSTM recurrence. 2 blocks (dir), 1024 threads = one gate row each.
// ---------------------------------------------------------------------------
__global__ __launch_bounds__(1024)
void script_rec(const unsigned* __restrict__ Wp, const float* __restrict__ xgs,
                float* __restrict__ semb) {
    int dir = blockIdx.x;
    int j = threadIdx.x;
    __shared__ float hb[2][256];
    __shared__ float gs[1024];
    __shared__ float cs[256];
    if (j < 256) { hb[0][j] = 0.f; cs[j] = 0.f; }
    __syncthreads();
    const uint4* wrow = reinterpret_cast<const uint4*>(Wp + (size_t)dir * 1024 * 128 + (size_t)j * 128);
    int pb = 0;
    for (int t = 0; t < NSC; t++) {
        int te = dir ? (NSC - 1 - t) : t;
        float acc = xgs[(size_t)te * 2048 + dir * 1024 + j];
        const float* hp = hb[pb];
#pragma unroll 4
        for (int q = 0; q < 32; q++) {
            uint4 w4 = wrow[q];
            int k = q * 8;
            {
                __nv_bfloat162 bp = *reinterpret_cast<__nv_bfloat162*>(&w4.x);
                float2 f = __bfloat1622float2(bp);
                acc += f.x * hp[k] + f.y * hp[k + 1];
            }
            {
                __nv_bfloat162 bp = *reinterpret_cast<__nv_bfloat162*>(&w4.y);
                float2 f = __bfloat1622float2(bp);
                acc += f.x * hp[k + 2] + f.y * hp[k + 3];
            }
            {
                __nv_bfloat162 bp = *reinterpret_cast<__nv_bfloat162*>(&w4.z);
                float2 f = __bfloat1622float2(bp);
                acc += f.x * hp[k + 4] + f.y * hp[k + 5];
            }
            {
                __nv_bfloat162 bp = *reinterpret_cast<__nv_bfloat162*>(&w4.w);
                float2 f = __bfloat1622float2(bp);
                acc += f.x * hp[k + 6] + f.y * hp[k + 7];
            }
        }
        gs[j] = acc;
        __syncthreads();
        if (j < 256) {
            float ig = sigm(gs[j]);
            float fg = sigm(gs[256 + j]);
            float gg = tanhf(gs[512 + j]);
            float og = sigm(gs[768 + j]);
            float c = fg * cs[j] + ig * gg;
            cs[j] = c;
            float h = og * tanhf(c);
            hb[pb ^ 1][j] = h;
            semb[(size_t)te * SSD + dir * 256 + j] = h;
        }
        __syncthreads();
        pb ^= 1;
    }
}

// ---------------------------------------------------------------------------
// Modality attention pooling + L2 normalize. One block per scene.
// ---------------------------------------------------------------------------
__global__ __launch_bounds__(256)
void modpool(const float* __restrict__ X, const float* __restrict__ w,
             const float* __restrict__ b, float* __restrict__ out) {
    int n = blockIdx.x, tid = threadIdx.x;
    int lane = tid & 31, wp = tid >> 5;
    __shared__ float es[TSEG];
    __shared__ float wred[8];
    __shared__ float nrm;
    for (int t = wp; t < TSEG; t += 8) {
        const float* xr = X + ((size_t)n * TSEG + t) * SSD;
        float p = 0.f;
        for (int h = lane; h < SSD; h += 32) p += xr[h] * w[h];
#pragma unroll
        for (int o = 16; o; o >>= 1) p += __shfl_down_sync(0xffffffffu, p, o);
        if (lane == 0) es[t] = tanhf(p + b[0]);
    }
    __syncthreads();
    if (tid == 0) {
        float m = es[0];
        for (int q = 1; q < TSEG; q++) m = fmaxf(m, es[q]);
        float ssum = 0.f;
        for (int q = 0; q < TSEG; q++) { float ex = expf(es[q] - m); es[q] = ex; ssum += ex; }
        float inv = 1.0f / ssum;
        for (int q = 0; q < TSEG; q++) es[q] *= inv;
    }
    __syncthreads();
    float v0 = 0.f, v1 = 0.f;
    const float* xb = X + (size_t)n * TSEG * SSD;
#pragma unroll 4
    for (int t = 0; t < TSEG; t++) {
        float a = es[t];
        v0 += a * xb[(size_t)t * SSD + tid];
        v1 += a * xb[(size_t)t * SSD + tid + 256];
    }
    float sq = v0 * v0 + v1 * v1;
#pragma unroll
    for (int o = 16; o; o >>= 1) sq += __shfl_down_sync(0xffffffffu, sq, o);
    if (lane == 0) wred[wp] = sq;
    __syncthreads();
    if (tid == 0) {
        float ssum = 0.f;
        for (int q = 0; q < 8; q++) ssum += wred[q];
        nrm = fmaxf(sqrtf(ssum), 1e-12f);
    }
    __syncthreads();
    out[(size_t)n * SSD + tid] = v0 / nrm;
    out[(size_t)n * SSD + tid + 256] = v1 / nrm;
}

// ---------------------------------------------------------------------------
// Cross-modal attention rows/cols. Block per scene.
// ---------------------------------------------------------------------------
__global__ __launch_bounds__(256)
void cross_att(const float* __restrict__ va, const float* __restrict__ M1,
               const float* __restrict__ M2, float* __restrict__ av, int mode) {
    int i = blockIdx.x, tid = threadIdx.x;
    __shared__ float p[NSC];
    __shared__ float red[256];
    float lm = -1e30f;
    for (int j = tid; j < NSC; j += 256) {
        float x = (mode == 0) ? va[(size_t)i * NSC + j] : va[(size_t)j * NSC + i];
        p[j] = x;
        lm = fmaxf(lm, x);
    }
    red[tid] = lm;
    __syncthreads();
    for (int s = 128; s; s >>= 1) {
        if (tid < s) red[tid] = fmaxf(red[tid], red[tid + s]);
        __syncthreads();
    }
    float m = red[0];
    __syncthreads();
    float ls = 0.f;
    for (int j = tid; j < NSC; j += 256) {
        float ex = expf(p[j] - m);
        p[j] = ex;
        ls += ex;
    }
    red[tid] = ls;
    __syncthreads();
    for (int s = 128; s; s >>= 1) {
        if (tid < s) red[tid] += red[tid + s];
        __syncthreads();
    }
    float inv = 1.0f / red[0];
    __syncthreads();
    int obase = (mode == 0) ? 512 : 0;
    for (int h = tid; h < SSD; h += 256) {
        float a = 0.f;
#pragma unroll 4
        for (int j = 0; j < NSC; j++) a += p[j] * M1[(size_t)j * SSD + h];
        av[(size_t)i * 1024 + obase + h] = a * inv + M2[(size_t)i * SSD + h];
    }
}

// ---------------------------------------------------------------------------
// core/nei scalars
// ---------------------------------------------------------------------------
__global__ __launch_bounds__(128)
void core_nei(const float* __restrict__ semb, const float* __restrict__ cw,
              const float* __restrict__ cb, const float* __restrict__ nw,
              const float* __restrict__ nb, float* __restrict__ core,
              float* __restrict__ nei) {
    int n = blockIdx.x, tid = threadIdx.x;
    __shared__ float r1[128], r2[128];
    float a = 0.f, b2 = 0.f;
    for (int h = tid; h < SSD; h += 128) {
        float s = semb[(size_t)n * SSD + h];
        a += s * cw[h];
        b2 += s * nw[h];
    }
    r1[tid] = a; r2[tid] = b2;
    __syncthreads();
    for (int s = 64; s; s >>= 1) {
        if (tid < s) { r1[tid] += r1[tid + s]; r2[tid] += r2[tid + s]; }
        __syncthreads();
    }
    if (tid == 0) {
        core[n] = tanhf(r1[0] + cb[0]);
        nei[n] = tanhf(r2[0] + nb[0]);
    }
}

__global__ void scores_mul(const float* __restrict__ core, const float* __restrict__ nei,
                           const float* __restrict__ mm, float* __restrict__ scores) {
    int id = blockIdx.x * 256 + threadIdx.x;
    if (id >= NSC * NSC) return;
    int n = id / NSC, j = id - n * NSC;
    scores[id] = core[n] * nei[j] * mm[id];
}

__global__ void col_mean(const float* __restrict__ scores, float* __restrict__ cm) {
    int j = blockIdx.x * 128 + threadIdx.x;
    if (j >= NSC) return;
    float s = 0.f;
    for (int n = 0; n < NSC; n++) s += scores[(size_t)n * NSC + j];
    cm[j] = s * (1.0f / NSC);
}

__global__ void col_sub(float* __restrict__ scores, const float* __restrict__ cm) {
    int id = blockIdx.x * 256 + threadIdx.x;
    if (id >= NSC * NSC) return;
    scores[id] -= cm[id % NSC];
}

// ---------------------------------------------------------------------------
// Top-6 neighbors per row + keep = argmax(nei_logits)+1. One warp per row.
// ---------------------------------------------------------------------------
__global__ __launch_bounds__(32)
void topk6(const float* __restrict__ scores, const float* __restrict__ nlog) {
    int n = blockIdx.x, lane = threadIdx.x;
    const float* row = scores + (size_t)n * NSC;
    int chosen[KMAX];
#pragma unroll
    for (int p = 0; p < KMAX; p++) chosen[p] = -1;
    for (int p = 0; p < KMAX; p++) {
        float bv = -1e30f;
        int bi = 1 << 30;
        for (int j = lane; j < NSC; j += 32) {
            bool used = false;
#pragma unroll
            for (int q = 0; q < KMAX; q++) used |= (q < p && chosen[q] == j);
            if (used) continue;
            float v = row[j];
            if (v > bv) { bv = v; bi = j; }
        }
#pragma unroll
        for (int o = 16; o; o >>= 1) {
            float ov = __shfl_down_sync(0xffffffffu, bv, o);
            int oi = __shfl_down_sync(0xffffffffu, bi, o);
            if (ov > bv || (ov == bv && oi < bi)) { bv = ov; bi = oi; }
        }
        bi = __shfl_sync(0xffffffffu, bi, 0);
        chosen[p] = bi;
        if (lane == 0) g_idx[n * KMAX + p] = bi;
    }
    if (lane == 0) {
        float bv = nlog[n * KMAX];
        int bk = 0;
        for (int q = 1; q < KMAX; q++) {
            float v = nlog[n * KMAX + q];
            if (v > bv) { bv = v; bk = q; }
        }
        g_keep[n] = bk + 1;
    }
}

__global__ __launch_bounds__(128)
void gather_gcn(const float* __restrict__ xw, const float* __restrict__ gb,
                float* __restrict__ gout) {
    int n = blockIdx.x, tid = threadIdx.x;
    int k = g_keep[n];
    int idx[KMAX];
#pragma unroll
    for (int p = 0; p < KMAX; p++) idx[p] = g_idx[n * KMAX + p];
    for (int h = tid; h < SSD; h += 128) {
        float a = gb[h];
        for (int p = 0; p < k; p++) a += xw[(size_t)idx[p] * SSD + h];
        gout[(size_t)n * SSD + h] = a;
    }
}

// ---------------------------------------------------------------------------
// TP heads
// ---------------------------------------------------------------------------
__global__ __launch_bounds__(128)
void tp_head(const float* __restrict__ semb, const float* __restrict__ gout,
             const float* __restrict__ W, const float* __restrict__ b,
             float* __restrict__ logits) {
    int n = blockIdx.x, tid = threadIdx.x;
    __shared__ float red[5][128];
    float acc[5] = {0, 0, 0, 0, 0};
    for (int jj = tid; jj < SSD; jj += 128) {
        float s = semb[(size_t)n * SSD + jj];
        float g = gout[(size_t)n * SSD + jj];
#pragma unroll
        for (int c = 0; c < 5; c++)
            acc[c] += s * W[(size_t)c * 1024 + jj] + g * W[(size_t)c * 1024 + 512 + jj];
    }
#pragma unroll
    for (int c = 0; c < 5; c++) red[c][tid] = acc[c];
    __syncthreads();
    for (int s2 = 64; s2; s2 >>= 1) {
        if (tid < s2) {
#pragma unroll
            for (int c = 0; c < 5; c++) red[c][tid] += red[c][tid + s2];
        }
        __syncthreads();
    }
    if (tid < 5) logits[n * 5 + tid] = red[tid][0] + b[tid];
}

__global__ __launch_bounds__(512)
void final_sm(const float* __restrict__ logits, float* __restrict__ out) {
    int c = blockIdx.x, tid = threadIdx.x;
    __shared__ float red[512];
    float v = (tid < NSC) ? logits[tid * 5 + c] : -1e30f;
    red[tid] = v;
    __syncthreads();
    for (int s = 256; s; s >>= 1) {
        if (tid < s) red[tid] = fmaxf(red[tid], red[tid + s]);
        __syncthreads();
    }
    float m = red[0];
    __syncthreads();
    float e = (tid < NSC) ? expf(v - m) : 0.f;
    red[tid] = e;
    __syncthreads();
    for (int s = 256; s; s >>= 1) {
        if (tid < s) red[tid] += red[tid + s];
        __syncthreads();
    }
    if (tid < NSC) out[c * NSC + tid] = e / red[0];
}

// ---------------------------------------------------------------------------
// Host launch
// ---------------------------------------------------------------------------
static void gemm_s(cudaStream_t st, const float* A, const float* B, const float* bias,
                   float* C, int M, int N, int K, int lda, int ldb, int ldc, int act) {
    dim3 g(M / 128, (N + 127) / 128);
    gemm128<<<g, 256, 0, st>>>(A, B, bias, C, M, N, K, lda, ldb, ldc, act);
}

extern "C" void kernel_launch(void* const* d_in, const int* in_sizes, int n_in,
                              void* d_out, int out_size) {
    // One-time stream/event creation (host objects only, no device memory).
    static cudaStream_t sA = nullptr, sB = nullptr;
    static cudaEvent_t eFork = nullptr, eA = nullptr, eB = nullptr;
    if (!sA) {
        cudaStreamCreateWithFlags(&sA, cudaStreamNonBlocking);
        cudaStreamCreateWithFlags(&sB, cudaStreamNonBlocking);
        cudaEventCreateWithFlags(&eFork, cudaEventDisableTiming);
        cudaEventCreateWithFlags(&eA, cudaEventDisableTiming);
        cudaEventCreateWithFlags(&eB, cudaEventDisableTiming);
    }

    bool dict = (in_sizes[3] == NSC);
    auto P = [&](int i) -> const void* {
        if (dict || i < 3) return d_in[i];
        if (i == 3) return d_in[n_in - 1];
        return d_in[i - 1];
    };
    const float* script   = (const float*)P(0);
    const float* audio    = (const float*)P(1);
    const float* vision   = (const float*)P(2);
    const int*   lens     = (const int*)  P(3);
    const float* sWih     = (const float*)P(4);
    const float* sWhh     = (const float*)P(5);
    const float* sb       = (const float*)P(6);
    const float* attnW    = (const float*)P(7);
    const float* attnb    = (const float*)P(8);
    const float* attnv    = (const float*)P(9);
    const float* scWih    = (const float*)P(10);
    const float* scWhh    = (const float*)P(11);
    const float* scb      = (const float*)P(12);
    const float* apW      = (const float*)P(13);
    const float* apb      = (const float*)P(14);
    const float* vpW      = (const float*)P(15);
    const float* vpb      = (const float*)P(16);
    const float* aaw      = (const float*)P(17);
    const float* aab      = (const float*)P(18);
    const float* avw      = (const float*)P(19);
    const float* avb      = (const float*)P(20);
    const float* corew    = (const float*)P(21);
    const float* coreb    = (const float*)P(22);
    const float* neiw     = (const float*)P(23);
    const float* neib     = (const float*)P(24);
    const float* ndW      = (const float*)P(25);
    const float* ndb      = (const float*)P(26);
    const float* gcnW     = (const float*)P(27);
    const float* gcnb     = (const float*)P(28);
    const float* tpW      = (const float*)P(29);
    const float* tpb      = (const float*)P(30);
    float* out = (float*)d_out;

    void* sp = nullptr;
    cudaGetSymbolAddress(&sp, g_scratch);
    float* S = (float*)sp;

    float*    xg     = S + OFF_XG;
    float*    outs   = S + OFF_OUTS;
    float*    E      = S + OFF_E;
    float*    semb   = S + OFF_SEMB;
    float*    xgs    = S + OFF_XGS;
    float*    scremb = S + OFF_SCREMB;
    float*    aud    = S + OFF_AUD;
    float*    vis    = S + OFF_VIS;
    float*    audv   = S + OFF_AUDV;
    float*    visv   = S + OFF_VISV;
    float*    va     = S + OFF_VA;
    float*    av     = S + OFF_AV;
    float*    mm     = S + OFF_MM;
    float*    scores = S + OFF_SCORES;
    float*    cmean  = S + OFF_CMEAN;
    float*    core   = S + OFF_CORE;
    float*    nei    = S + OFF_NEI;
    float*    nlog   = S + OFF_NLOG;
    float*    xw     = S + OFF_XW;
    float*    gout   = S + OFF_GOUT;
    float*    logits = S + OFF_LOGITS;
    float4*   packP  = (float4*)(S + OFF_PACK);
    unsigned* Wps    = (unsigned*)(S + OFF_WPS);
    float*    gcnT   = S + OFF_GCNT;

    // Fork both worker streams off the capture-origin (null) stream.
    cudaEventRecord(eFork, 0);
    cudaStreamWaitEvent(sA, eFork, 0);
    cudaStreamWaitEvent(sB, eFork, 0);

    // ---------------- Stream A: script chain ----------------
    prep_scene_whh<<<512, 256, 0, sA>>>(sWhh, packP);
    prep_script_whh<<<1024, 256, 0, sA>>>(scWhh, Wps);
    prep_transpose512<<<1024, 256, 0, sA>>>(gcnW, gcnT);

    gemm_s(sA, script, sWih, sb, xg, NSC * SLEN, 2048, DIN, DIN, DIN, 2048, 0);
    scene_rec<<<128, 256, 0, sA>>>(xg, packP, outs);
    gemm_s(sA, outs, attnW, attnb, E, NSC * SLEN, SSD, SSD, SSD, SSD, SSD, 1);
    attn_pool<<<NSC, 256, 0, sA>>>(E, attnv, outs, lens, semb);
    gemm_s(sA, semb, scWih, scb, xgs, NSC, 2048, SSD, SSD, SSD, 2048, 0);
    script_rec<<<2, 1024, 0, sA>>>(Wps, xgs, scremb);
    core_nei<<<NSC, 128, 0, sA>>>(semb, corew, coreb, neiw, neib, core, nei);
    gemm_s(sA, scremb, gcnT, nullptr, xw, NSC, SSD, SSD, SSD, SSD, SSD, 0);
    cudaEventRecord(eA, sA);

    // ---------------- Stream B: audio/vision branch ----------------
    gemm_s(sB, audio, apW, apb, aud, NSC * TSEG, SSD, AIN, AIN, AIN, SSD, 1);
    gemm_s(sB, vision, vpW, vpb, vis, NSC * TSEG, SSD, VIN, VIN, VIN, SSD, 1);
    modpool<<<NSC, 256, 0, sB>>>(aud, aaw, aab, audv);
    modpool<<<NSC, 256, 0, sB>>>(vis, avw, avb, visv);
    gemm_s(sB, visv, audv, nullptr, va, NSC, NSC, SSD, SSD, SSD, NSC, 0);
    cross_att<<<NSC, 256, 0, sB>>>(va, audv, visv, av, 0);
    cross_att<<<NSC, 256, 0, sB>>>(va, visv, audv, av, 1);
    gemm_s(sB, av, av, nullptr, mm, NSC, NSC, 1024, 1024, 1024, NSC, 0);
    cudaEventRecord(eB, sB);

    // ---------------- Join back onto the null stream; tail ----------------
    cudaStreamWaitEvent(0, eA, 0);
    cudaStreamWaitEvent(0, eB, 0);

    scores_mul<<<(NSC * NSC + 255) / 256, 256>>>(core, nei, mm, scores);
    col_mean<<<3, 128>>>(scores, cmean);
    col_sub<<<(NSC * NSC + 255) / 256, 256>>>(scores, cmean);
    gemm_s(0, scores, ndW, ndb, nlog, NSC, KMAX, NSC, NSC, PADW, KMAX, 0);
    topk6<<<NSC, 32>>>(scores, nlog);
    gather_gcn<<<NSC, 128>>>(xw, gcnb, gout);
    tp_head<<<NSC, 128>>>(scremb, gout, tpW, tpb, logits);
    final_sm<<<5, 512>>>(logits, out);
}

// round 16
// speedup vs baseline: 1.0296x; 1.0296x over previous
#include <cuda_runtime.h>
#include <cuda_bf16.h>
#include <math.h>
#include <stdint.h>

// ---------------------------------------------------------------------------
// Problem constants
// ---------------------------------------------------------------------------
#define NSC   384     // scenes
#define SLEN  64      // sentences per scene
#define DIN   768
#define TSEG  40      // audio/vision segments
#define AIN   128
#define VIN   2048
#define HID   256
#define SSD   512     // 2*HID
#define PADW  400
#define KMAX  6

// ---------------------------------------------------------------------------
// Scratch (one big static device buffer; offsets in floats)
// ---------------------------------------------------------------------------
#define OFF_XG      0ull           // 24576 x 2048
#define OFF_OUTS    50331648ull    // 24576 x 512
#define OFF_E       62914560ull    // 24576 x 512
#define OFF_SEMB    75497472ull    // 384 x 512   scene_emb
#define OFF_XGS     75694080ull    // 384 x 2048
#define OFF_SCREMB  76480512ull    // 384 x 512   script_emb
#define OFF_AUD     76677120ull    // 15360 x 512
#define OFF_VIS     84541440ull    // 15360 x 512
#define OFF_AUDV    92405760ull    // 384 x 512
#define OFF_VISV    92602368ull    // 384 x 512
#define OFF_VA      92798976ull    // 384 x 384
#define OFF_AV      92946432ull    // 384 x 1024
#define OFF_MM      93339648ull    // 384 x 384
#define OFF_SCORES  93487104ull    // 384 x 384
#define OFF_CMEAN   93634560ull    // 384 (+pad)
#define OFF_CORE    93635072ull    // 384 (+pad)
#define OFF_NEI     93635584ull    // 384 (+pad)
#define OFF_NLOG    93636096ull    // 384 x 6 (+pad)
#define OFF_XW      93638656ull    // 384 x 512
#define OFF_GOUT    93835264ull    // 384 x 512
#define OFF_LOGITS  94031872ull    // 384 x 5 (+pad)
#define OFF_PACK    94033920ull    // scene Whh packed: 2*256*256 float4
#define OFF_WPS     94558208ull    // script Whh bf16x2: 2*1024*128 uint
#define OFF_GCNT    94820352ull    // gcn_W transposed 512x512
#define SCR_TOTAL   95082496ull

__device__ __align__(256) float g_scratch[SCR_TOTAL];
__device__ int g_idx[NSC * KMAX];
__device__ int g_keep[NSC];

__device__ __forceinline__ float sigm(float x) { return 1.0f / (1.0f + expf(-x)); }

// ---------------------------------------------------------------------------
// Prep kernels (weight repacking)
// ---------------------------------------------------------------------------

__global__ void prep_scene_whh(const float* __restrict__ Whh, float4* __restrict__ P) {
    int id = blockIdx.x * 256 + threadIdx.x;       // 2*256*256 = 131072
    if (id >= 2 * 256 * 256) return;
    int u = id & 255, k = (id >> 8) & 255, dir = id >> 16;
    const float* W = Whh + (size_t)dir * 1024 * 256;
    float4 v;
    v.x = W[(size_t)(0 * 256 + u) * 256 + k];
    v.y = W[(size_t)(1 * 256 + u) * 256 + k];
    v.z = W[(size_t)(2 * 256 + u) * 256 + k];
    v.w = W[(size_t)(3 * 256 + u) * 256 + k];
    P[id] = v;
}

__global__ void prep_script_whh(const float* __restrict__ Whh, unsigned* __restrict__ Wp) {
    int id = blockIdx.x * 256 + threadIdx.x;       // 2*1024*128 = 262144
    if (id >= 2 * 1024 * 128) return;
    int k2 = id & 127, j = (id >> 7) & 1023, dir = id >> 17;
    size_t base = ((size_t)(dir * 1024 + j)) * 256 + 2 * k2;
    __nv_bfloat162 t;
    t.x = __float2bfloat16(Whh[base]);
    t.y = __float2bfloat16(Whh[base + 1]);
    Wp[id] = *reinterpret_cast<unsigned*>(&t);
}

__global__ void prep_transpose512(const float* __restrict__ W, float* __restrict__ Wt) {
    int id = blockIdx.x * 256 + threadIdx.x;
    if (id >= 512 * 512) return;
    int r = id >> 9, c = id & 511;
    Wt[(size_t)c * 512 + r] = W[id];
}

// ---------------------------------------------------------------------------
// 3xTF32 tensor-core GEMM: C[M,N] = act(A[M,K] @ B[N,K]^T + bias[N])
// Error-compensated: A = Ah + Al, B = Bh + Bl (tf32 hi/lo split);
// acc += Ah*Bh + Ah*Bl + Al*Bh  (fp32-level precision, ~2^-21 per op).
// M % 128 == 0, N % 64 == 0, K % 32 == 0, bias non-null. act: 0=none, 1=tanh.
// 256 threads, 8 warps (4x2), warp tile 32x32, m16n8k8, double-buffered smem.
// ---------------------------------------------------------------------------
#define TF3_SMEM_BYTES ((4*32*132 + 4*32*68) * 4)   // 102,400 B

__device__ __forceinline__ float to_tf32(float x) {
    unsigned u;
    asm("cvt.rna.tf32.f32 %0, %1;" : "=r"(u) : "f"(x));
    return __uint_as_float(u);
}

__device__ __forceinline__ void mma_tf32(float* d, const unsigned* a, const unsigned* b) {
    asm volatile(
        "mma.sync.aligned.m16n8k8.row.col.f32.tf32.tf32.f32 "
        "{%0,%1,%2,%3}, {%4,%5,%6,%7}, {%8,%9}, {%0,%1,%2,%3};\n"
        : "+f"(d[0]), "+f"(d[1]), "+f"(d[2]), "+f"(d[3])
        : "r"(a[0]), "r"(a[1]), "r"(a[2]), "r"(a[3]), "r"(b[0]), "r"(b[1]));
}

__global__ __launch_bounds__(256)
void gemm_3x(const float* __restrict__ A, const float* __restrict__ B,
             const float* __restrict__ bias, float* __restrict__ C,
             int M, int N, int K, int lda, int ldb, int ldc, int act) {
    extern __shared__ float sm[];
    float (*Ah)[32][132] = reinterpret_cast<float(*)[32][132]>(sm);
    float (*Al)[32][132] = reinterpret_cast<float(*)[32][132]>(sm + 2 * 32 * 132);
    float (*Bh)[32][68]  = reinterpret_cast<float(*)[32][68]>(sm + 4 * 32 * 132);
    float (*Bl)[32][68]  = reinterpret_cast<float(*)[32][68]>(sm + 4 * 32 * 132 + 2 * 32 * 68);

    int tid = threadIdx.x;
    int m0 = blockIdx.x * 128, n0 = blockIdx.y * 64;
    int warp = tid >> 5, lane = tid & 31;
    int wm = warp >> 1, wn = warp & 1;
    int lq = lane & 3, g = lane >> 2;

    int arow = tid >> 3;            // 0..31
    int acol = (tid & 7) * 4;       // 0..28
    int sxo = (tid & 7) << 2;       // staging swizzle

    const float* Ab = A + (size_t)(m0 + arow) * lda + acol;
    const float* Bb = B + (size_t)(n0 + arow) * ldb + acol;

    float acc[2][4][4];
#pragma unroll
    for (int mi = 0; mi < 2; mi++)
#pragma unroll
        for (int ni = 0; ni < 4; ni++)
#pragma unroll
            for (int r = 0; r < 4; r++) acc[mi][ni][r] = 0.0f;

    int nk = K >> 5;

    // stage chunk 0 into buf 0
    {
#pragma unroll
        for (int p = 0; p < 4; p++) {
            float4 v = *reinterpret_cast<const float4*>(Ab + (size_t)(32 * p) * lda);
            int ph = (arow + 32 * p) ^ sxo;
            float h0 = to_tf32(v.x), h1 = to_tf32(v.y), h2 = to_tf32(v.z), h3 = to_tf32(v.w);
            Ah[0][acol + 0][ph] = h0; Al[0][acol + 0][ph] = to_tf32(v.x - h0);
            Ah[0][acol + 1][ph] = h1; Al[0][acol + 1][ph] = to_tf32(v.y - h1);
            Ah[0][acol + 2][ph] = h2; Al[0][acol + 2][ph] = to_tf32(v.z - h2);
            Ah[0][acol + 3][ph] = h3; Al[0][acol + 3][ph] = to_tf32(v.w - h3);
        }
#pragma unroll
        for (int p = 0; p < 2; p++) {
            float4 v = *reinterpret_cast<const float4*>(Bb + (size_t)(32 * p) * ldb);
            int ph = (arow + 32 * p) ^ sxo;
            float h0 = to_tf32(v.x), h1 = to_tf32(v.y), h2 = to_tf32(v.z), h3 = to_tf32(v.w);
            Bh[0][acol + 0][ph] = h0; Bl[0][acol + 0][ph] = to_tf32(v.x - h0);
            Bh[0][acol + 1][ph] = h1; Bl[0][acol + 1][ph] = to_tf32(v.y - h1);
            Bh[0][acol + 2][ph] = h2; Bl[0][acol + 2][ph] = to_tf32(v.z - h2);
            Bh[0][acol + 3][ph] = h3; Bl[0][acol + 3][ph] = to_tf32(v.w - h3);
        }
    }
    __syncthreads();

    int buf = 0;
    for (int kb = 0; kb < nk; kb++) {
        float4 pa[4], pb[2];
        bool more = (kb + 1 < nk);
        if (more) {
            const float* Ap = Ab + (kb + 1) * 32;
            const float* Bp = Bb + (kb + 1) * 32;
#pragma unroll
            for (int p = 0; p < 4; p++)
                pa[p] = *reinterpret_cast<const float4*>(Ap + (size_t)(32 * p) * lda);
#pragma unroll
            for (int p = 0; p < 2; p++)
                pb[p] = *reinterpret_cast<const float4*>(Bp + (size_t)(32 * p) * ldb);
        }

#pragma unroll
        for (int ks = 0; ks < 4; ks++) {
            int k8 = ks * 8;
            int xo0 = ((k8 >> 2) & 7) << 2;
            int xo1 = (((k8 >> 2) + 1) & 7) << 2;
            unsigned afh[2][4], afl[2][4], bfh[4][2], bfl[4][2];
#pragma unroll
            for (int mi = 0; mi < 2; mi++) {
                int rb = wm * 32 + mi * 16;
                int i00 = (rb + g) ^ xo0, i10 = (rb + 8 + g) ^ xo0;
                int i01 = (rb + g) ^ xo1, i11 = (rb + 8 + g) ^ xo1;
                afh[mi][0] = __float_as_uint(Ah[buf][k8 + lq][i00]);
                afh[mi][1] = __float_as_uint(Ah[buf][k8 + lq][i10]);
                afh[mi][2] = __float_as_uint(Ah[buf][k8 + 4 + lq][i01]);
                afh[mi][3] = __float_as_uint(Ah[buf][k8 + 4 + lq][i11]);
                afl[mi][0] = __float_as_uint(Al[buf][k8 + lq][i00]);
                afl[mi][1] = __float_as_uint(Al[buf][k8 + lq][i10]);
                afl[mi][2] = __float_as_uint(Al[buf][k8 + 4 + lq][i01]);
                afl[mi][3] = __float_as_uint(Al[buf][k8 + 4 + lq][i11]);
            }
#pragma unroll
            for (int ni = 0; ni < 4; ni++) {
                int cb = wn * 32 + ni * 8;
                int j0 = (cb + g) ^ xo0, j1 = (cb + g) ^ xo1;
                bfh[ni][0] = __float_as_uint(Bh[buf][k8 + lq][j0]);
                bfh[ni][1] = __float_as_uint(Bh[buf][k8 + 4 + lq][j1]);
                bfl[ni][0] = __float_as_uint(Bl[buf][k8 + lq][j0]);
                bfl[ni][1] = __float_as_uint(Bl[buf][k8 + 4 + lq][j1]);
            }
#pragma unroll
            for (int mi = 0; mi < 2; mi++)
#pragma unroll
                for (int ni = 0; ni < 4; ni++) {
                    mma_tf32(acc[mi][ni], afh[mi], bfl[ni]);
                    mma_tf32(acc[mi][ni], afl[mi], bfh[ni]);
                    mma_tf32(acc[mi][ni], afh[mi], bfh[ni]);
                }
        }

        if (more) {
            int nb = buf ^ 1;
#pragma unroll
            for (int p = 0; p < 4; p++) {
                int ph = (arow + 32 * p) ^ sxo;
                float h0 = to_tf32(pa[p].x), h1 = to_tf32(pa[p].y);
                float h2 = to_tf32(pa[p].z), h3 = to_tf32(pa[p].w);
                Ah[nb][acol + 0][ph] = h0; Al[nb][acol + 0][ph] = to_tf32(pa[p].x - h0);
                Ah[nb][acol + 1][ph] = h1; Al[nb][acol + 1][ph] = to_tf32(pa[p].y - h1);
                Ah[nb][acol + 2][ph] = h2; Al[nb][acol + 2][ph] = to_tf32(pa[p].z - h2);
                Ah[nb][acol + 3][ph] = h3; Al[nb][acol + 3][ph] = to_tf32(pa[p].w - h3);
            }
#pragma unroll
            for (int p = 0; p < 2; p++) {
                int ph = (arow + 32 * p) ^ sxo;
                float h0 = to_tf32(pb[p].x), h1 = to_tf32(pb[p].y);
                float h2 = to_tf32(pb[p].z), h3 = to_tf32(pb[p].w);
                Bh[nb][acol + 0][ph] = h0; Bl[nb][acol + 0][ph] = to_tf32(pb[p].x - h0);
                Bh[nb][acol + 1][ph] = h1; Bl[nb][acol + 1][ph] = to_tf32(pb[p].y - h1);
                Bh[nb][acol + 2][ph] = h2; Bl[nb][acol + 2][ph] = to_tf32(pb[p].z - h2);
                Bh[nb][acol + 3][ph] = h3; Bl[nb][acol + 3][ph] = to_tf32(pb[p].w - h3);
            }
        }
        __syncthreads();
        buf ^= 1;
    }

    // epilogue
#pragma unroll
    for (int mi = 0; mi < 2; mi++) {
#pragma unroll
        for (int ni = 0; ni < 4; ni++) {
            int r0 = m0 + wm * 32 + mi * 16 + g;
            int cc = n0 + wn * 32 + ni * 8 + 2 * lq;
            float b0 = bias[cc], b1 = bias[cc + 1];
            float v0 = acc[mi][ni][0] + b0;
            float v1 = acc[mi][ni][1] + b1;
            float v2 = acc[mi][ni][2] + b0;
            float v3 = acc[mi][ni][3] + b1;
            if (act == 1) {
                v0 = tanhf(v0); v1 = tanhf(v1); v2 = tanhf(v2); v3 = tanhf(v3);
            }
            *reinterpret_cast<float2*>(&C[(size_t)r0 * ldc + cc]) = make_float2(v0, v1);
            *reinterpret_cast<float2*>(&C[(size_t)(r0 + 8) * ldc + cc]) = make_float2(v2, v3);
        }
    }
}

// ---------------------------------------------------------------------------
// fp32 SIMT GEMM (small / decision-path shapes): C = act(A@B^T + bias)
// Block tile 128x64, BK=16, 256 threads, 8x4 per thread, double-buffered.
// M % 128 == 0, K % 16 == 0. N bounds-checked. bias may be null.
// ---------------------------------------------------------------------------
__global__ __launch_bounds__(256)
void gemm128(const float* __restrict__ A, const float* __restrict__ B,
             const float* __restrict__ bias, float* __restrict__ C,
             int M, int N, int K, int lda, int ldb, int ldc, int act) {
    __shared__ float As[2][16][132];
    __shared__ float Bs[2][16][68];
    int tid = threadIdx.x;
    int m0 = blockIdx.x * 128, n0 = blockIdx.y * 64;
    int tx = tid & 15, ty = tid >> 4;
    int ldr = tid >> 2;
    int ldk = (tid & 3) * 4;

    const float* Ab = A + (size_t)(m0 + ldr) * lda + ldk;
    const float* Bb = B + (size_t)(n0 + ldr) * ldb + ldk;
    bool bval = (n0 + ldr) < N;

    float acc[8][4];
#pragma unroll
    for (int i = 0; i < 8; i++)
#pragma unroll
        for (int j = 0; j < 4; j++) acc[i][j] = 0.0f;

    {
        float4 a0 = *reinterpret_cast<const float4*>(Ab);
        float4 a1 = *reinterpret_cast<const float4*>(Ab + (size_t)64 * lda);
        float4 b0 = make_float4(0.f, 0.f, 0.f, 0.f);
        if (bval) b0 = *reinterpret_cast<const float4*>(Bb);
        As[0][ldk + 0][ldr] = a0.x; As[0][ldk + 1][ldr] = a0.y;
        As[0][ldk + 2][ldr] = a0.z; As[0][ldk + 3][ldr] = a0.w;
        As[0][ldk + 0][ldr + 64] = a1.x; As[0][ldk + 1][ldr + 64] = a1.y;
        As[0][ldk + 2][ldr + 64] = a1.z; As[0][ldk + 3][ldr + 64] = a1.w;
        Bs[0][ldk + 0][ldr] = b0.x; Bs[0][ldk + 1][ldr] = b0.y;
        Bs[0][ldk + 2][ldr] = b0.z; Bs[0][ldk + 3][ldr] = b0.w;
    }
    __syncthreads();

    int nk = K >> 4;
    int buf = 0;
    for (int kb = 0; kb < nk; kb++) {
        float4 pa0, pa1, pb0;
        bool more = (kb + 1 < nk);
        if (more) {
            const float* Ap = Ab + (kb + 1) * 16;
            const float* Bp = Bb + (kb + 1) * 16;
            pa0 = *reinterpret_cast<const float4*>(Ap);
            pa1 = *reinterpret_cast<const float4*>(Ap + (size_t)64 * lda);
            pb0 = make_float4(0.f, 0.f, 0.f, 0.f);
            if (bval) pb0 = *reinterpret_cast<const float4*>(Bp);
        }

#pragma unroll
        for (int k = 0; k < 16; k++) {
            float4 av0 = *reinterpret_cast<const float4*>(&As[buf][k][ty * 8]);
            float4 av1 = *reinterpret_cast<const float4*>(&As[buf][k][ty * 8 + 4]);
            float4 bv  = *reinterpret_cast<const float4*>(&Bs[buf][k][tx * 4]);
            float ar[8] = {av0.x, av0.y, av0.z, av0.w, av1.x, av1.y, av1.z, av1.w};
            float br[4] = {bv.x, bv.y, bv.z, bv.w};
#pragma unroll
            for (int i = 0; i < 8; i++)
#pragma unroll
                for (int j = 0; j < 4; j++) acc[i][j] += ar[i] * br[j];
        }

        if (more) {
            int nb = buf ^ 1;
            As[nb][ldk + 0][ldr] = pa0.x; As[nb][ldk + 1][ldr] = pa0.y;
            As[nb][ldk + 2][ldr] = pa0.z; As[nb][ldk + 3][ldr] = pa0.w;
            As[nb][ldk + 0][ldr + 64] = pa1.x; As[nb][ldk + 1][ldr + 64] = pa1.y;
            As[nb][ldk + 2][ldr + 64] = pa1.z; As[nb][ldk + 3][ldr + 64] = pa1.w;
            Bs[nb][ldk + 0][ldr] = pb0.x; Bs[nb][ldk + 1][ldr] = pb0.y;
            Bs[nb][ldk + 2][ldr] = pb0.z; Bs[nb][ldk + 3][ldr] = pb0.w;
        }
        __syncthreads();
        buf ^= 1;
    }

#pragma unroll
    for (int i = 0; i < 8; i++) {
        int row = m0 + ty * 8 + i;
#pragma unroll
        for (int j = 0; j < 4; j++) {
            int col = n0 + tx * 4 + j;
            if (col < N) {
                float v = acc[i][j];
                if (bias) v += bias[col];
                if (act == 1) v = tanhf(v);
                C[(size_t)row * ldc + col] = v;
            }
        }
    }
}

// ---------------------------------------------------------------------------
// Scene BiLSTM recurrence. 128 blocks: dir = bx/64, group = bx%64 (6 scenes).
// ---------------------------------------------------------------------------
__global__ __launch_bounds__(256)
void scene_rec(const float* __restrict__ xg, const float4* __restrict__ P,
               float* __restrict__ outs) {
    int dir = blockIdx.x >> 6;
    int grp = blockIdx.x & 63;
    int u = threadIdx.x;
    int nbase = grp * 6;
    __shared__ float hbuf[2][256][6];
#pragma unroll
    for (int sc = 0; sc < 6; sc++) hbuf[0][u][sc] = 0.0f;
    __syncthreads();
    float c[6] = {0, 0, 0, 0, 0, 0};
    const float4* Pd = P + (size_t)dir * 256 * 256;
    int pb = 0;
    for (int t = 0; t < SLEN; t++) {
        int te = dir ? (SLEN - 1 - t) : t;
        float4 acc[6];
#pragma unroll
        for (int sc = 0; sc < 6; sc++) {
            const float* xr = xg + ((size_t)(nbase + sc) * SLEN + te) * 2048 + dir * 1024 + u;
            acc[sc].x = xr[0];
            acc[sc].y = xr[256];
            acc[sc].z = xr[512];
            acc[sc].w = xr[768];
        }
#pragma unroll 4
        for (int k = 0; k < 256; k++) {
            float4 w = Pd[(size_t)k * 256 + u];
#pragma unroll
            for (int sc = 0; sc < 6; sc++) {
                float hv = hbuf[pb][k][sc];
                acc[sc].x += w.x * hv;
                acc[sc].y += w.y * hv;
                acc[sc].z += w.z * hv;
                acc[sc].w += w.w * hv;
            }
        }
#pragma unroll
        for (int sc = 0; sc < 6; sc++) {
            float ig = sigm(acc[sc].x);
            float fg = sigm(acc[sc].y);
            float gg = tanhf(acc[sc].z);
            float og = sigm(acc[sc].w);
            c[sc] = fg * c[sc] + ig * gg;
            float h = og * tanhf(c[sc]);
            hbuf[pb ^ 1][u][sc] = h;
            outs[((size_t)(nbase + sc) * SLEN + te) * SSD + dir * 256 + u] = h;
        }
        __syncthreads();
        pb ^= 1;
    }
}

// ---------------------------------------------------------------------------
// Attention pooling over sentences -> scene_emb. One block per scene.
// ---------------------------------------------------------------------------
__global__ __launch_bounds__(256)
void attn_pool(const float* __restrict__ E, const float* __restrict__ av,
               const float* __restrict__ outs, const int* __restrict__ lens,
               float* __restrict__ semb) {
    int n = blockIdx.x, tid = threadIdx.x;
    __shared__ float pe[4][64];
    __shared__ float sa[64];
    int s = tid & 63, ch = tid >> 6;
    const float* er = E + ((size_t)n * SLEN + s) * SSD + ch * 128;
    float p = 0.f;
#pragma unroll 8
    for (int h = 0; h < 128; h++) p += er[h] * av[ch * 128 + h];
    pe[ch][s] = p;
    __syncthreads();
    if (tid < 64) {
        int len = lens[n]; if (len < 1) len = 1;
        float e = pe[0][tid] + pe[1][tid] + pe[2][tid] + pe[3][tid];
        sa[tid] = (tid < len) ? e : -1e9f;
    }
    __syncthreads();
    if (tid == 0) {
        float m = sa[0];
        for (int q = 1; q < 64; q++) m = fmaxf(m, sa[q]);
        float ssum = 0.f;
        for (int q = 0; q < 64; q++) { float ex = expf(sa[q] - m); sa[q] = ex; ssum += ex; }
        float inv = 1.0f / ssum;
        for (int q = 0; q < 64; q++) sa[q] *= inv;
    }
    __syncthreads();
    for (int h = tid; h < SSD; h += 256) {
        float a = 0.f;
        const float* orow = outs + (size_t)n * SLEN * SSD + h;
#pragma unroll 8
        for (int q = 0; q < 64; q++) a += sa[q] * orow[(size_t)q * SSD];
        semb[(size_t)n * SSD + h] = a;
    }
}

// ---------------------------------------------------------------------------
// Script BiLSTM recurrence. 2 blocks (dir), 1024 threads = one gate row each.
// ---------------------------------------------------------------------------
__global__ __launch_bounds__(1024)
void script_rec(const unsigned* __restrict__ Wp, const float* __restrict__ xgs,
                float* __restrict__ semb) {
    int dir = blockIdx.x;
    int j = threadIdx.x;
    __shared__ float hb[2][256];
    __shared__ float gs[1024];
    __shared__ float cs[256];
    if (j < 256) { hb[0][j] = 0.f; cs[j] = 0.f; }
    __syncthreads();
    const uint4* wrow = reinterpret_cast<const uint4*>(Wp + (size_t)dir * 1024 * 128 + (size_t)j * 128);
    int pb = 0;
    for (int t = 0; t < NSC; t++) {
        int te = dir ? (NSC - 1 - t) : t;
        float acc = xgs[(size_t)te * 2048 + dir * 1024 + j];
        const float* hp = hb[pb];
#pragma unroll 4
        for (int q = 0; q < 32; q++) {
            uint4 w4 = wrow[q];
            int k = q * 8;
            {
                __nv_bfloat162 bp = *reinterpret_cast<__nv_bfloat162*>(&w4.x);
                float2 f = __bfloat1622float2(bp);
                acc += f.x * hp[k] + f.y * hp[k + 1];
            }
            {
                __nv_bfloat162 bp = *reinterpret_cast<__nv_bfloat162*>(&w4.y);
                float2 f = __bfloat1622float2(bp);
                acc += f.x * hp[k + 2] + f.y * hp[k + 3];
            }
            {
                __nv_bfloat162 bp = *reinterpret_cast<__nv_bfloat162*>(&w4.z);
                float2 f = __bfloat1622float2(bp);
                acc += f.x * hp[k + 4] + f.y * hp[k + 5];
            }
            {
                __nv_bfloat162 bp = *reinterpret_cast<__nv_bfloat162*>(&w4.w);
                float2 f = __bfloat1622float2(bp);
                acc += f.x * hp[k + 6] + f.y * hp[k + 7];
            }
        }
        gs[j] = acc;
        __syncthreads();
        if (j < 256) {
            float ig = sigm(gs[j]);
            float fg = sigm(gs[256 + j]);
            float gg = tanhf(gs[512 + j]);
            float og = sigm(gs[768 + j]);
            float c = fg * cs[j] + ig * gg;
            cs[j] = c;
            float h = og * tanhf(c);
            hb[pb ^ 1][j] = h;
            semb[(size_t)te * SSD + dir * 256 + j] = h;
        }
        __syncthreads();
        pb ^= 1;
    }
}

// ---------------------------------------------------------------------------
// Modality attention pooling + L2 normalize. One block per scene.
// ---------------------------------------------------------------------------
__global__ __launch_bounds__(256)
void modpool(const float* __restrict__ X, const float* __restrict__ w,
             const float* __restrict__ b, float* __restrict__ out) {
    int n = blockIdx.x, tid = threadIdx.x;
    int lane = tid & 31, wp = tid >> 5;
    __shared__ float es[TSEG];
    __shared__ float wred[8];
    __shared__ float nrm;
    for (int t = wp; t < TSEG; t += 8) {
        const float* xr = X + ((size_t)n * TSEG + t) * SSD;
        float p = 0.f;
        for (int h = lane; h < SSD; h += 32) p += xr[h] * w[h];
#pragma unroll
        for (int o = 16; o; o >>= 1) p += __shfl_down_sync(0xffffffffu, p, o);
        if (lane == 0) es[t] = tanhf(p + b[0]);
    }
    __syncthreads();
    if (tid == 0) {
        float m = es[0];
        for (int q = 1; q < TSEG; q++) m = fmaxf(m, es[q]);
        float ssum = 0.f;
        for (int q = 0; q < TSEG; q++) { float ex = expf(es[q] - m); es[q] = ex; ssum += ex; }
        float inv = 1.0f / ssum;
        for (int q = 0; q < TSEG; q++) es[q] *= inv;
    }
    __syncthreads();
    float v0 = 0.f, v1 = 0.f;
    const float* xb = X + (size_t)n * TSEG * SSD;
#pragma unroll 4
    for (int t = 0; t < TSEG; t++) {
        float a = es[t];
        v0 += a * xb[(size_t)t * SSD + tid];
        v1 += a * xb[(size_t)t * SSD + tid + 256];
    }
    float sq = v0 * v0 + v1 * v1;
#pragma unroll
    for (int o = 16; o; o >>= 1) sq += __shfl_down_sync(0xffffffffu, sq, o);
    if (lane == 0) wred[wp] = sq;
    __syncthreads();
    if (tid == 0) {
        float ssum = 0.f;
        for (int q = 0; q < 8; q++) ssum += wred[q];
        nrm = fmaxf(sqrtf(ssum), 1e-12f);
    }
    __syncthreads();
    out[(size_t)n * SSD + tid] = v0 / nrm;
    out[(size_t)n * SSD + tid + 256] = v1 / nrm;
}

// ---------------------------------------------------------------------------
// Cross-modal attention rows/cols. Block per scene.
// ---------------------------------------------------------------------------
__global__ __launch_bounds__(256)
void cross_att(const float* __restrict__ va, const float* __restrict__ M1,
               const float* __restrict__ M2, float* __restrict__ av, int mode) {
    int i = blockIdx.x, tid = threadIdx.x;
    __shared__ float p[NSC];
    __shared__ float red[256];
    float lm = -1e30f;
    for (int j = tid; j < NSC; j += 256) {
        float x = (mode == 0) ? va[(size_t)i * NSC + j] : va[(size_t)j * NSC + i];
        p[j] = x;
        lm = fmaxf(lm, x);
    }
    red[tid] = lm;
    __syncthreads();
    for (int s = 128; s; s >>= 1) {
        if (tid < s) red[tid] = fmaxf(red[tid], red[tid + s]);
        __syncthreads();
    }
    float m = red[0];
    __syncthreads();
    float ls = 0.f;
    for (int j = tid; j < NSC; j += 256) {
        float ex = expf(p[j] - m);
        p[j] = ex;
        ls += ex;
    }
    red[tid] = ls;
    __syncthreads();
    for (int s = 128; s; s >>= 1) {
        if (tid < s) red[tid] += red[tid + s];
        __syncthreads();
    }
    float inv = 1.0f / red[0];
    __syncthreads();
    int obase = (mode == 0) ? 512 : 0;
    for (int h = tid; h < SSD; h += 256) {
        float a = 0.f;
#pragma unroll 4
        for (int j = 0; j < NSC; j++) a += p[j] * M1[(size_t)j * SSD + h];
        av[(size_t)i * 1024 + obase + h] = a * inv + M2[(size_t)i * SSD + h];
    }
}

// ---------------------------------------------------------------------------
// core/nei scalars
// ---------------------------------------------------------------------------
__global__ __launch_bounds__(128)
void core_nei(const float* __restrict__ semb, const float* __restrict__ cw,
              const float* __restrict__ cb, const float* __restrict__ nw,
              const float* __restrict__ nb, float* __restrict__ core,
              float* __restrict__ nei) {
    int n = blockIdx.x, tid = threadIdx.x;
    __shared__ float r1[128], r2[128];
    float a = 0.f, b2 = 0.f;
    for (int h = tid; h < SSD; h += 128) {
        float s = semb[(size_t)n * SSD + h];
        a += s * cw[h];
        b2 += s * nw[h];
    }
    r1[tid] = a; r2[tid] = b2;
    __syncthreads();
    for (int s = 64; s; s >>= 1) {
        if (tid < s) { r1[tid] += r1[tid + s]; r2[tid] += r2[tid + s]; }
        __syncthreads();
    }
    if (tid == 0) {
        core[n] = tanhf(r1[0] + cb[0]);
        nei[n] = tanhf(r2[0] + nb[0]);
    }
}

__global__ void scores_mul(const float* __restrict__ core, const float* __restrict__ nei,
                           const float* __restrict__ mm, float* __restrict__ scores) {
    int id = blockIdx.x * 256 + threadIdx.x;
    if (id >= NSC * NSC) return;
    int n = id / NSC, j = id - n * NSC;
    scores[id] = core[n] * nei[j] * mm[id];
}

__global__ void col_mean(const float* __restrict__ scores, float* __restrict__ cm) {
    int j = blockIdx.x * 128 + threadIdx.x;
    if (j >= NSC) return;
    float s = 0.f;
    for (int n = 0; n < NSC; n++) s += scores[(size_t)n * NSC + j];
    cm[j] = s * (1.0f / NSC);
}

__global__ void col_sub(float* __restrict__ scores, const float* __restrict__ cm) {
    int id = blockIdx.x * 256 + threadIdx.x;
    if (id >= NSC * NSC) return;
    scores[id] -= cm[id % NSC];
}

// ---------------------------------------------------------------------------
// Top-6 neighbors per row + keep = argmax(nei_logits)+1. One warp per row.
// ---------------------------------------------------------------------------
__global__ __launch_bounds__(32)
void topk6(const float* __restrict__ scores, const float* __restrict__ nlog) {
    int n = blockIdx.x, lane = threadIdx.x;
    const float* row = scores + (size_t)n * NSC;
    int chosen[KMAX];
#pragma unroll
    for (int p = 0; p < KMAX; p++) chosen[p] = -1;
    for (int p = 0; p < KMAX; p++) {
        float bv = -1e30f;
        int bi = 1 << 30;
        for (int j = lane; j < NSC; j += 32) {
            bool used = false;
#pragma unroll
            for (int q = 0; q < KMAX; q++) used |= (q < p && chosen[q] == j);
            if (used) continue;
            float v = row[j];
            if (v > bv) { bv = v; bi = j; }
        }
#pragma unroll
        for (int o = 16; o; o >>= 1) {
            float ov = __shfl_down_sync(0xffffffffu, bv, o);
            int oi = __shfl_down_sync(0xffffffffu, bi, o);
            if (ov > bv || (ov == bv && oi < bi)) { bv = ov; bi = oi; }
        }
        bi = __shfl_sync(0xffffffffu, bi, 0);
        chosen[p] = bi;
        if (lane == 0) g_idx[n * KMAX + p] = bi;
    }
    if (lane == 0) {
        float bv = nlog[n * KMAX];
        int bk = 0;
        for (int q = 1; q < KMAX; q++) {
            float v = nlog[n * KMAX + q];
            if (v > bv) { bv = v; bk = q; }
        }
        g_keep[n] = bk + 1;
    }
}

__global__ __launch_bounds__(128)
void gather_gcn(const float* __restrict__ xw, const float* __restrict__ gb,
                float* __restrict__ gout) {
    int n = blockIdx.x, tid = threadIdx.x;
    int k = g_keep[n];
    int idx[KMAX];
#pragma unroll
    for (int p = 0; p < KMAX; p++) idx[p] = g_idx[n * KMAX + p];
    for (int h = tid; h < SSD; h += 128) {
        float a = gb[h];
        for (int p = 0; p < k; p++) a += xw[(size_t)idx[p] * SSD + h];
        gout[(size_t)n * SSD + h] = a;
    }
}

// ---------------------------------------------------------------------------
// TP heads
// ---------------------------------------------------------------------------
__global__ __launch_bounds__(128)
void tp_head(const float* __restrict__ semb, const float* __restrict__ gout,
             const float* __restrict__ W, const float* __restrict__ b,
             float* __restrict__ logits) {
    int n = blockIdx.x, tid = threadIdx.x;
    __shared__ float red[5][128];
    float acc[5] = {0, 0, 0, 0, 0};
    for (int jj = tid; jj < SSD; jj += 128) {
        float s = semb[(size_t)n * SSD + jj];
        float g = gout[(size_t)n * SSD + jj];
#pragma unroll
        for (int c = 0; c < 5; c++)
            acc[c] += s * W[(size_t)c * 1024 + jj] + g * W[(size_t)c * 1024 + 512 + jj];
    }
#pragma unroll
    for (int c = 0; c < 5; c++) red[c][tid] = acc[c];
    __syncthreads();
    for (int s2 = 64; s2; s2 >>= 1) {
        if (tid < s2) {
#pragma unroll
            for (int c = 0; c < 5; c++) red[c][tid] += red[c][tid + s2];
        }
        __syncthreads();
    }
    if (tid < 5) logits[n * 5 + tid] = red[tid][0] + b[tid];
}

__global__ __launch_bounds__(512)
void final_sm(const float* __restrict__ logits, float* __restrict__ out) {
    int c = blockIdx.x, tid = threadIdx.x;
    __shared__ float red[512];
    float v = (tid < NSC) ? logits[tid * 5 + c] : -1e30f;
    red[tid] = v;
    __syncthreads();
    for (int s = 256; s; s >>= 1) {
        if (tid < s) red[tid] = fmaxf(red[tid], red[tid + s]);
        __syncthreads();
    }
    float m = red[0];
    __syncthreads();
    float e = (tid < NSC) ? expf(v - m) : 0.f;
    red[tid] = e;
    __syncthreads();
    for (int s = 256; s; s >>= 1) {
        if (tid < s) red[tid] += red[tid + s];
        __syncthreads();
    }
    if (tid < NSC) out[c * NSC + tid] = e / red[0];
}

// ---------------------------------------------------------------------------
// Host launch
// ---------------------------------------------------------------------------
static void gemm_s(cudaStream_t st, const float* A, const float* B, const float* bias,
                   float* C, int M, int N, int K, int lda, int ldb, int ldc, int act) {
    dim3 g(M / 128, (N + 63) / 64);
    gemm128<<<g, 256, 0, st>>>(A, B, bias, C, M, N, K, lda, ldb, ldc, act);
}

static void gemm3_s(cudaStream_t st, const float* A, const float* B, const float* bias,
                    float* C, int M, int N, int K, int lda, int ldb, int ldc, int act) {
    dim3 g(M / 128, N / 64);
    gemm_3x<<<g, 256, TF3_SMEM_BYTES, st>>>(A, B, bias, C, M, N, K, lda, ldb, ldc, act);
}

extern "C" void kernel_launch(void* const* d_in, const int* in_sizes, int n_in,
                              void* d_out, int out_size) {
    static cudaStream_t sA = nullptr, sB = nullptr;
    static cudaEvent_t eFork = nullptr, eA = nullptr, eB = nullptr;
    if (!sA) {
        cudaStreamCreateWithFlags(&sA, cudaStreamNonBlocking);
        cudaStreamCreateWithFlags(&sB, cudaStreamNonBlocking);
        cudaEventCreateWithFlags(&eFork, cudaEventDisableTiming);
        cudaEventCreateWithFlags(&eA, cudaEventDisableTiming);
        cudaEventCreateWithFlags(&eB, cudaEventDisableTiming);
        cudaFuncSetAttribute(gemm_3x, cudaFuncAttributeMaxDynamicSharedMemorySize,
                             TF3_SMEM_BYTES);
    }

    bool dict = (in_sizes[3] == NSC);
    auto P = [&](int i) -> const void* {
        if (dict || i < 3) return d_in[i];
        if (i == 3) return d_in[n_in - 1];
        return d_in[i - 1];
    };
    const float* script   = (const float*)P(0);
    const float* audio    = (const float*)P(1);
    const float* vision   = (const float*)P(2);
    const int*   lens     = (const int*)  P(3);
    const float* sWih     = (const float*)P(4);
    const float* sWhh     = (const float*)P(5);
    const float* sb       = (const float*)P(6);
    const float* attnW    = (const float*)P(7);
    const float* attnb    = (const float*)P(8);
    const float* attnv    = (const float*)P(9);
    const float* scWih    = (const float*)P(10);
    const float* scWhh    = (const float*)P(11);
    const float* scb      = (const float*)P(12);
    const float* apW      = (const float*)P(13);
    const float* apb      = (const float*)P(14);
    const float* vpW      = (const float*)P(15);
    const float* vpb      = (const float*)P(16);
    const float* aaw      = (const float*)P(17);
    const float* aab      = (const float*)P(18);
    const float* avw      = (const float*)P(19);
    const float* avb      = (const float*)P(20);
    const float* corew    = (const float*)P(21);
    const float* coreb    = (const float*)P(22);
    const float* neiw     = (const float*)P(23);
    const float* neib     = (const float*)P(24);
    const float* ndW      = (const float*)P(25);
    const float* ndb      = (const float*)P(26);
    const float* gcnW     = (const float*)P(27);
    const float* gcnb     = (const float*)P(28);
    const float* tpW      = (const float*)P(29);
    const float* tpb      = (const float*)P(30);
    float* out = (float*)d_out;

    void* sp = nullptr;
    cudaGetSymbolAddress(&sp, g_scratch);
    float* S = (float*)sp;

    float*    xg     = S + OFF_XG;
    float*    outs   = S + OFF_OUTS;
    float*    E      = S + OFF_E;
    float*    semb   = S + OFF_SEMB;
    float*    xgs    = S + OFF_XGS;
    float*    scremb = S + OFF_SCREMB;
    float*    aud    = S + OFF_AUD;
    float*    vis    = S + OFF_VIS;
    float*    audv   = S + OFF_AUDV;
    float*    visv   = S + OFF_VISV;
    float*    va     = S + OFF_VA;
    float*    av     = S + OFF_AV;
    float*    mm     = S + OFF_MM;
    float*    scores = S + OFF_SCORES;
    float*    cmean  = S + OFF_CMEAN;
    float*    core   = S + OFF_CORE;
    float*    nei    = S + OFF_NEI;
    float*    nlog   = S + OFF_NLOG;
    float*    xw     = S + OFF_XW;
    float*    gout   = S + OFF_GOUT;
    float*    logits = S + OFF_LOGITS;
    float4*   packP  = (float4*)(S + OFF_PACK);
    unsigned* Wps    = (unsigned*)(S + OFF_WPS);
    float*    gcnT   = S + OFF_GCNT;

    // Fork both worker streams off the capture-origin (null) stream.
    cudaEventRecord(eFork, 0);
    cudaStreamWaitEvent(sA, eFork, 0);
    cudaStreamWaitEvent(sB, eFork, 0);

    // ---------------- Stream A: script chain ----------------
    prep_scene_whh<<<512, 256, 0, sA>>>(sWhh, packP);
    prep_script_whh<<<1024, 256, 0, sA>>>(scWhh, Wps);
    prep_transpose512<<<1024, 256, 0, sA>>>(gcnW, gcnT);

    gemm3_s(sA, script, sWih, sb, xg, NSC * SLEN, 2048, DIN, DIN, DIN, 2048, 0);
    scene_rec<<<128, 256, 0, sA>>>(xg, packP, outs);
    gemm3_s(sA, outs, attnW, attnb, E, NSC * SLEN, SSD, SSD, SSD, SSD, SSD, 1);
    attn_pool<<<NSC, 256, 0, sA>>>(E, attnv, outs, lens, semb);
    gemm3_s(sA, semb, scWih, scb, xgs, NSC, 2048, SSD, SSD, SSD, 2048, 0);
    script_rec<<<2, 1024, 0, sA>>>(Wps, xgs, scremb);
    core_nei<<<NSC, 128, 0, sA>>>(semb, corew, coreb, neiw, neib, core, nei);
    gemm_s(sA, scremb, gcnT, nullptr, xw, NSC, SSD, SSD, SSD, SSD, SSD, 0);
    cudaEventRecord(eA, sA);

    // ---------------- Stream B: audio/vision branch ----------------
    gemm3_s(sB, audio, apW, apb, aud, NSC * TSEG, SSD, AIN, AIN, AIN, SSD, 1);
    gemm3_s(sB, vision, vpW, vpb, vis, NSC * TSEG, SSD, VIN, VIN, VIN, SSD, 1);
    modpool<<<NSC, 256, 0, sB>>>(aud, aaw, aab, audv);
    modpool<<<NSC, 256, 0, sB>>>(vis, avw, avb, visv);
    gemm_s(sB, visv, audv, nullptr, va, NSC, NSC, SSD, SSD, SSD, NSC, 0);
    cross_att<<<NSC, 256, 0, sB>>>(va, audv, visv, av, 0);
    cross_att<<<NSC, 256, 0, sB>>>(va, visv, audv, av, 1);
    gemm_s(sB, av, av, nullptr, mm, NSC, NSC, 1024, 1024, 1024, NSC, 0);
    cudaEventRecord(eB, sB);

    // ---------------- Join back onto the null stream; tail ----------------
    cudaStreamWaitEvent(0, eA, 0);
    cudaStreamWaitEvent(0, eB, 0);

    scores_mul<<<(NSC * NSC + 255) / 256, 256>>>(core, nei, mm, scores);
    col_mean<<<3, 128>>>(scores, cmean);
    col_sub<<<(NSC * NSC + 255) / 256, 256>>>(scores, cmean);
    gemm_s(0, scores, ndW, ndb, nlog, NSC, KMAX, NSC, NSC, PADW, KMAX, 0);
    topk6<<<NSC, 32>>>(scores, nlog);
    gather_gcn<<<NSC, 128>>>(xw, gcnb, gout);
    tp_head<<<NSC, 128>>>(scremb, gout, tpW, tpb, logits);
    final_sm<<<5, 512>>>(logits, out);
}